// round 3
// baseline (speedup 1.0000x reference)
#include <cuda_runtime.h>
#include <math.h>

// Problem constants
#define NB    4
#define SQ    2048
#define DIMM  1024
#define INNERD 1024
#define MTOK  (NB * SQ)          // 8192

// Scratch (allocation-free rule: __device__ globals)
__device__ float g_qkv[(size_t)MTOK * 3 * INNERD];   // 96 MB  [8192, 3072]
__device__ float g_att[(size_t)NB * SQ * SQ];        // 64 MB  [4, 2048, 2048]
__device__ float g_ao [(size_t)MTOK * INNERD];       // 32 MB  [8192, 1024]

__device__ __forceinline__ unsigned f2tf(float x) {
    unsigned r;
    asm("cvt.rna.tf32.f32 %0, %1;" : "=r"(r) : "f"(x));
    return r;
}

__device__ __forceinline__ void mma8(float* c, const unsigned* a, const unsigned* b) {
    asm volatile(
        "mma.sync.aligned.m16n8k8.row.col.f32.tf32.tf32.f32 "
        "{%0,%1,%2,%3}, {%4,%5,%6,%7}, {%8,%9}, {%0,%1,%2,%3};\n"
        : "+f"(c[0]), "+f"(c[1]), "+f"(c[2]), "+f"(c[3])
        : "r"(a[0]), "r"(a[1]), "r"(a[2]), "r"(a[3]), "r"(b[0]), "r"(b[1]));
}

// Generic 3xTF32 GEMM: C = alpha * (A @ opB) (+ bias), fp32-accurate via
// big/small split (terms Ab*Bb + Ab*Bs + As*Bb; dropped As*Bs <= 2^-22).
//   BT = true : B stored [N, K] row-major (contract along its rows' k)  -> C = A @ B^T
//   BT = false: B stored [K, N] row-major                               -> C = A @ B
// Tiles: 128(M) x 128(N) x 32(K). 256 threads = 8 warps in 4x2; warp tile 32x64.
// All problem dims here are exact multiples -> no bounds checks.
template <bool BT>
__global__ __launch_bounds__(256)
void gemm3(const float* __restrict__ A, const float* __restrict__ B,
           float* __restrict__ C, const float* __restrict__ bias,
           int K, int lda, int ldb, int ldc,
           long long sA, long long sB, long long sC, float alpha)
{
    __shared__ float As[128][36];   // pad to 36: fragment LDS conflict-free
    __shared__ float Bs[128][36];   // stored [n][k]

    const int tid = threadIdx.x;
    const int m0 = blockIdx.y * 128;
    const int n0 = blockIdx.x * 128;
    A += (long long)blockIdx.z * sA;
    B += (long long)blockIdx.z * sB;
    C += (long long)blockIdx.z * sC;

    const int warp = tid >> 5, lane = tid & 31;
    const int wm = warp >> 1;          // 0..3
    const int wn = warp & 1;           // 0..1
    const int gid = lane >> 2, tig = lane & 3;

    float acc[2][8][4];
    #pragma unroll
    for (int i = 0; i < 2; i++)
        #pragma unroll
        for (int j = 0; j < 8; j++)
            #pragma unroll
            for (int q = 0; q < 4; q++) acc[i][j][q] = 0.f;

    for (int k0 = 0; k0 < K; k0 += 32) {
        // --- A tile: 128 rows x 32 cols, coalesced along k ---
        #pragma unroll
        for (int i = 0; i < 16; i++) {
            int idx = tid + i * 256;
            int r = idx >> 5, c = idx & 31;
            As[r][c] = A[(long long)(m0 + r) * lda + (k0 + c)];
        }
        // --- B tile into Bs[n][k] ---
        if (BT) {
            #pragma unroll
            for (int i = 0; i < 16; i++) {
                int idx = tid + i * 256;
                int r = idx >> 5, c = idx & 31;      // r = n, c = k
                Bs[r][c] = B[(long long)(n0 + r) * ldb + (k0 + c)];
            }
        } else {
            #pragma unroll
            for (int i = 0; i < 16; i++) {
                int idx = tid + i * 256;
                int r = idx >> 7, c = idx & 127;     // r = k (0..31), c = n
                Bs[c][r] = B[(long long)(k0 + r) * ldb + (n0 + c)];
            }
        }
        __syncthreads();

        #pragma unroll
        for (int ks = 0; ks < 4; ks++) {
            const int kk = ks * 8;
            unsigned ab[2][4], asm_[2][4];
            #pragma unroll
            for (int mi = 0; mi < 2; mi++) {
                const int rb = wm * 32 + mi * 16;
                float v0 = As[rb + gid    ][kk + tig    ];
                float v1 = As[rb + gid + 8][kk + tig    ];
                float v2 = As[rb + gid    ][kk + tig + 4];
                float v3 = As[rb + gid + 8][kk + tig + 4];
                ab[mi][0] = f2tf(v0); asm_[mi][0] = f2tf(v0 - __uint_as_float(ab[mi][0]));
                ab[mi][1] = f2tf(v1); asm_[mi][1] = f2tf(v1 - __uint_as_float(ab[mi][1]));
                ab[mi][2] = f2tf(v2); asm_[mi][2] = f2tf(v2 - __uint_as_float(ab[mi][2]));
                ab[mi][3] = f2tf(v3); asm_[mi][3] = f2tf(v3 - __uint_as_float(ab[mi][3]));
            }
            #pragma unroll
            for (int ni = 0; ni < 8; ni++) {
                const int nr = wn * 64 + ni * 8 + gid;
                float w0 = Bs[nr][kk + tig];
                float w1 = Bs[nr][kk + tig + 4];
                unsigned bb[2], bs[2];
                bb[0] = f2tf(w0); bs[0] = f2tf(w0 - __uint_as_float(bb[0]));
                bb[1] = f2tf(w1); bs[1] = f2tf(w1 - __uint_as_float(bb[1]));
                #pragma unroll
                for (int mi = 0; mi < 2; mi++) {
                    mma8(acc[mi][ni], ab[mi],  bb);
                    mma8(acc[mi][ni], ab[mi],  bs);
                    mma8(acc[mi][ni], asm_[mi], bb);
                }
            }
        }
        __syncthreads();
    }

    // Epilogue: C layout m16n8 f32 fragments
    #pragma unroll
    for (int mi = 0; mi < 2; mi++) {
        #pragma unroll
        for (int ni = 0; ni < 8; ni++) {
            const int col  = n0 + wn * 64 + ni * 8 + 2 * tig;
            const int row0 = m0 + wm * 32 + mi * 16 + gid;
            float b0v = bias ? bias[col]     : 0.f;
            float b1v = bias ? bias[col + 1] : 0.f;
            C[(long long)row0 * ldc + col    ]      = acc[mi][ni][0] * alpha + b0v;
            C[(long long)row0 * ldc + col + 1]      = acc[mi][ni][1] * alpha + b1v;
            C[(long long)(row0 + 8) * ldc + col    ] = acc[mi][ni][2] * alpha + b0v;
            C[(long long)(row0 + 8) * ldc + col + 1] = acc[mi][ni][3] * alpha + b1v;
        }
    }
}

// Row softmax over 2048-wide rows; one block per row.
__global__ __launch_bounds__(256)
void softmax_rows(float* __restrict__ P)
{
    float* row = P + (long long)blockIdx.x * 2048;
    const int t = threadIdx.x;
    float v[8];
    float mx = -1e30f;
    #pragma unroll
    for (int j = 0; j < 8; j++) { v[j] = row[t + j * 256]; mx = fmaxf(mx, v[j]); }

    __shared__ float red[256];
    red[t] = mx; __syncthreads();
    for (int s = 128; s > 0; s >>= 1) {
        if (t < s) red[t] = fmaxf(red[t], red[t + s]);
        __syncthreads();
    }
    mx = red[0]; __syncthreads();

    float sum = 0.f;
    #pragma unroll
    for (int j = 0; j < 8; j++) { v[j] = __expf(v[j] - mx); sum += v[j]; }
    red[t] = sum; __syncthreads();
    for (int s = 128; s > 0; s >>= 1) {
        if (t < s) red[t] += red[t + s];
        __syncthreads();
    }
    const float inv = 1.f / red[0];
    #pragma unroll
    for (int j = 0; j < 8; j++) row[t + j * 256] = v[j] * inv;
}

extern "C" void kernel_launch(void* const* d_in, const int* in_sizes, int n_in,
                              void* d_out, int out_size)
{
    const float* x    = (const float*)d_in[0];   // [4, 2048, 1024]
    const float* Wqkv = (const float*)d_in[1];   // [1024, 3072]
    const float* Wout = (const float*)d_in[2];   // [1024, 1024]
    const float* bout = (const float*)d_in[3];   // [1024]
    float* out = (float*)d_out;                  // [4, 2048, 1024]

    float *qkv, *att, *ao;
    cudaGetSymbolAddress((void**)&qkv, g_qkv);
    cudaGetSymbolAddress((void**)&att, g_att);
    cudaGetSymbolAddress((void**)&ao,  g_ao);

    const dim3 blk(256);
    const long long sQK = (long long)SQ * 3 * INNERD;   // per-batch stride in qkv
    const long long sAT = (long long)SQ * SQ;
    const long long sAO = (long long)SQ * INNERD;

    // 1) qkv = x @ W_qkv                 [8192,1024] x [1024,3072] (NN)
    gemm3<false><<<dim3(3 * INNERD / 128, MTOK / 128, 1), blk>>>(
        x, Wqkv, qkv, nullptr,
        DIMM, DIMM, 3 * INNERD, 3 * INNERD, 0, 0, 0, 1.f);

    // 2) logits = (Q @ K^T) * scale, per batch        (NT: K stored [n=2048, k=1024])
    gemm3<true><<<dim3(SQ / 128, SQ / 128, NB), blk>>>(
        qkv, qkv + INNERD, att, nullptr,
        INNERD, 3 * INNERD, 3 * INNERD, SQ, sQK, sQK, sAT, 0.125f);

    // 3) softmax rows
    softmax_rows<<<NB * SQ, blk>>>(att);

    // 4) ao = attn @ V, per batch        (NN: V stored [k=2048, n=1024] with ld 3072)
    gemm3<false><<<dim3(INNERD / 128, SQ / 128, NB), blk>>>(
        att, qkv + 2 * INNERD, ao, nullptr,
        SQ, SQ, 3 * INNERD, INNERD, sAT, sQK, sAO, 1.f);

    // 5) out = ao @ W_out + b_out        (NN)
    gemm3<false><<<dim3(DIMM / 128, MTOK / 128, 1), blk>>>(
        ao, Wout, out, bout,
        INNERD, INNERD, DIMM, DIMM, 0, 0, 0, 1.f);
}

// round 4
// speedup vs baseline: 1.9894x; 1.9894x over previous
#include <cuda_runtime.h>
#include <cuda_bf16.h>
#include <math.h>

// Problem constants
#define NB     4
#define SQ     2048
#define DIMM   1024
#define INNERD 1024
#define MTOK   (NB * SQ)          // 8192

// Scratch (allocation-free rule: __device__ globals)
__device__ float g_qkv[(size_t)MTOK * 3 * INNERD];   // 96 MB  [8192, 3072]
__device__ float g_att[(size_t)NB * SQ * SQ];        // 64 MB  [4, 2048, 2048]
__device__ float g_ao [(size_t)MTOK * INNERD];       // 32 MB  [8192, 1024]

// SMEM word index for tile arrays stored as [128 rows][16 u32-words] with an
// XOR swizzle that is conflict-free for BOTH the store patterns (row-major
// fill and the [k][n]->[n][k] transpose scatter) and all mma fragment loads.
__device__ __forceinline__ int sidx(int row, int q) {
    return row * 16 + (q ^ ((row & 7) << 1) ^ ((row >> 3) & 3));
}

// Split two fp32 into packed bf16 hi pair + bf16 lo (residual) pair.
// Low 16 bits of each u32 = first element (even k) -> matches mma layout.
__device__ __forceinline__ void split2(float x0, float x1, unsigned& h, unsigned& l) {
    __nv_bfloat162 hh = __floats2bfloat162_rn(x0, x1);
    float r0 = x0 - __low2float(hh);
    float r1 = x1 - __high2float(hh);
    __nv_bfloat162 ll = __floats2bfloat162_rn(r0, r1);
    h = *reinterpret_cast<unsigned*>(&hh);
    l = *reinterpret_cast<unsigned*>(&ll);
}

__device__ __forceinline__ void mma16(float* c, const unsigned* a, unsigned b0, unsigned b1) {
    asm volatile(
        "mma.sync.aligned.m16n8k16.row.col.f32.bf16.bf16.f32 "
        "{%0,%1,%2,%3}, {%4,%5,%6,%7}, {%8,%9}, {%0,%1,%2,%3};\n"
        : "+f"(c[0]), "+f"(c[1]), "+f"(c[2]), "+f"(c[3])
        : "r"(a[0]), "r"(a[1]), "r"(a[2]), "r"(a[3]), "r"(b0), "r"(b1));
}

// 3xBF16 error-compensated GEMM: C = alpha * (A @ opB) (+ bias).
//   BT = true : B stored [N, K] row-major  -> C = A @ B^T
//   BT = false: B stored [K, N] row-major  -> C = A @ B
// Tiles 128x128x32, 256 threads (8 warps 4x2), warp tile 32x64.
// bf16 hi/lo tiles precomputed in SMEM; register-staged global prefetch.
template <bool BT>
__global__ __launch_bounds__(256)
void gemm_bf3(const float* __restrict__ A, const float* __restrict__ B,
              float* __restrict__ C, const float* __restrict__ bias,
              int K, int lda, int ldb, int ldc,
              long long sA, long long sB, long long sC, float alpha)
{
    __shared__ unsigned Ah[2048], Al[2048], Bh[2048], Bl[2048];   // 4 x 8KB

    const int tid = threadIdx.x;
    const int m0 = blockIdx.y * 128;
    const int n0 = blockIdx.x * 128;
    A += (long long)blockIdx.z * sA + (long long)m0 * lda;
    B += (long long)blockIdx.z * sB;
    C += (long long)blockIdx.z * sC;

    const int warp = tid >> 5, lane = tid & 31;
    const int wm = warp >> 1;          // 0..3
    const int wn = warp & 1;           // 0..1
    const int gid = lane >> 2, tig = lane & 3;

    float acc[2][8][4] = {};

    // Staging registers for the next tile
    float2 ra[8], rb[8];

    // A-style mapping (rows x 16 k-pairs): idx = tid + i*256
    const int ar  = tid >> 4;          // base row (+= 16 per i)
    const int acp = tid & 15;          // k-pair index
    // B NN mapping: idx over (16 k-pairs x 128 n)
    const int bpr0 = tid >> 7;         // base k-pair (+= 2 per i)
    const int bc   = tid & 127;        // n

    auto loadA = [&](int k0) {
        #pragma unroll
        for (int i = 0; i < 8; i++) {
            int r = ar + i * 16;
            ra[i] = *(const float2*)(A + (long long)r * lda + k0 + 2 * acp);
        }
    };
    auto loadB = [&](int k0) {
        if (BT) {
            #pragma unroll
            for (int i = 0; i < 8; i++) {
                int r = ar + i * 16;
                rb[i] = *(const float2*)(B + (long long)(n0 + r) * ldb + k0 + 2 * acp);
            }
        } else {
            #pragma unroll
            for (int i = 0; i < 8; i++) {
                int pr = bpr0 + i * 2;
                const float* p = B + (long long)(k0 + 2 * pr) * ldb + n0 + bc;
                rb[i].x = p[0];
                rb[i].y = p[ldb];
            }
        }
    };
    auto stsTiles = [&]() {
        #pragma unroll
        for (int i = 0; i < 8; i++) {
            int r = ar + i * 16;
            unsigned h, l;
            split2(ra[i].x, ra[i].y, h, l);
            Ah[sidx(r, acp)] = h;
            Al[sidx(r, acp)] = l;
        }
        if (BT) {
            #pragma unroll
            for (int i = 0; i < 8; i++) {
                int r = ar + i * 16;
                unsigned h, l;
                split2(rb[i].x, rb[i].y, h, l);
                Bh[sidx(r, acp)] = h;
                Bl[sidx(r, acp)] = l;
            }
        } else {
            #pragma unroll
            for (int i = 0; i < 8; i++) {
                int pr = bpr0 + i * 2;
                unsigned h, l;
                split2(rb[i].x, rb[i].y, h, l);
                Bh[sidx(bc, pr)] = h;
                Bl[sidx(bc, pr)] = l;
            }
        }
    };

    loadA(0);
    loadB(0);

    for (int k0 = 0; k0 < K; k0 += 32) {
        __syncthreads();          // previous tile fully consumed
        stsTiles();               // convert + store current tile (consumes regs)
        __syncthreads();
        if (k0 + 32 < K) { loadA(k0 + 32); loadB(k0 + 32); }   // prefetch overlaps compute

        #pragma unroll
        for (int ks = 0; ks < 2; ks++) {
            const int qb = ks * 8;
            unsigned ah[2][4], al[2][4];
            #pragma unroll
            for (int mi = 0; mi < 2; mi++) {
                int r0 = wm * 32 + mi * 16 + gid;
                int r1 = r0 + 8;
                ah[mi][0] = Ah[sidx(r0, qb + tig)];
                ah[mi][1] = Ah[sidx(r1, qb + tig)];
                ah[mi][2] = Ah[sidx(r0, qb + 4 + tig)];
                ah[mi][3] = Ah[sidx(r1, qb + 4 + tig)];
                al[mi][0] = Al[sidx(r0, qb + tig)];
                al[mi][1] = Al[sidx(r1, qb + tig)];
                al[mi][2] = Al[sidx(r0, qb + 4 + tig)];
                al[mi][3] = Al[sidx(r1, qb + 4 + tig)];
            }
            #pragma unroll
            for (int ni = 0; ni < 8; ni++) {
                int nr = wn * 64 + ni * 8 + gid;
                unsigned bh0 = Bh[sidx(nr, qb + tig)];
                unsigned bh1 = Bh[sidx(nr, qb + 4 + tig)];
                unsigned bl0 = Bl[sidx(nr, qb + tig)];
                unsigned bl1 = Bl[sidx(nr, qb + 4 + tig)];
                #pragma unroll
                for (int mi = 0; mi < 2; mi++) {
                    mma16(acc[mi][ni], ah[mi], bh0, bh1);   // Ah*Bh
                    mma16(acc[mi][ni], ah[mi], bl0, bl1);   // Ah*Bl
                    mma16(acc[mi][ni], al[mi], bh0, bh1);   // Al*Bh
                }
            }
        }
    }

    // Epilogue: m16n8 f32 fragment layout; vectorized pair stores.
    #pragma unroll
    for (int mi = 0; mi < 2; mi++) {
        #pragma unroll
        for (int ni = 0; ni < 8; ni++) {
            const int col  = n0 + wn * 64 + ni * 8 + 2 * tig;
            const int row0 = m0 + wm * 32 + mi * 16 + gid;
            float b0v = bias ? bias[col]     : 0.f;
            float b1v = bias ? bias[col + 1] : 0.f;
            float2 v0 = make_float2(acc[mi][ni][0] * alpha + b0v,
                                    acc[mi][ni][1] * alpha + b1v);
            float2 v1 = make_float2(acc[mi][ni][2] * alpha + b0v,
                                    acc[mi][ni][3] * alpha + b1v);
            *(float2*)(C + (long long)row0 * ldc + col)       = v0;
            *(float2*)(C + (long long)(row0 + 8) * ldc + col) = v1;
        }
    }
}

// Row softmax over 2048-wide rows; one block per row.
__global__ __launch_bounds__(256)
void softmax_rows(float* __restrict__ P)
{
    float* row = P + (long long)blockIdx.x * 2048;
    const int t = threadIdx.x;
    float v[8];
    float mx = -1e30f;
    #pragma unroll
    for (int j = 0; j < 8; j++) { v[j] = row[t + j * 256]; mx = fmaxf(mx, v[j]); }

    __shared__ float red[256];
    red[t] = mx; __syncthreads();
    for (int s = 128; s > 0; s >>= 1) {
        if (t < s) red[t] = fmaxf(red[t], red[t + s]);
        __syncthreads();
    }
    mx = red[0]; __syncthreads();

    float sum = 0.f;
    #pragma unroll
    for (int j = 0; j < 8; j++) { v[j] = __expf(v[j] - mx); sum += v[j]; }
    red[t] = sum; __syncthreads();
    for (int s = 128; s > 0; s >>= 1) {
        if (t < s) red[t] += red[t + s];
        __syncthreads();
    }
    const float inv = 1.f / red[0];
    #pragma unroll
    for (int j = 0; j < 8; j++) row[t + j * 256] = v[j] * inv;
}

extern "C" void kernel_launch(void* const* d_in, const int* in_sizes, int n_in,
                              void* d_out, int out_size)
{
    const float* x    = (const float*)d_in[0];   // [4, 2048, 1024]
    const float* Wqkv = (const float*)d_in[1];   // [1024, 3072]
    const float* Wout = (const float*)d_in[2];   // [1024, 1024]
    const float* bout = (const float*)d_in[3];   // [1024]
    float* out = (float*)d_out;                  // [4, 2048, 1024]

    float *qkv, *att, *ao;
    cudaGetSymbolAddress((void**)&qkv, g_qkv);
    cudaGetSymbolAddress((void**)&att, g_att);
    cudaGetSymbolAddress((void**)&ao,  g_ao);

    const dim3 blk(256);
    const long long sQK = (long long)SQ * 3 * INNERD;   // per-batch stride in qkv
    const long long sAT = (long long)SQ * SQ;
    const long long sAO = (long long)SQ * INNERD;

    // 1) qkv = x @ W_qkv                 [8192,1024] x [1024,3072] (NN)
    gemm_bf3<false><<<dim3(3 * INNERD / 128, MTOK / 128, 1), blk>>>(
        x, Wqkv, qkv, nullptr,
        DIMM, DIMM, 3 * INNERD, 3 * INNERD, 0, 0, 0, 1.f);

    // 2) logits = (Q @ K^T) * scale, per batch   (NT: K stored [n=2048, k=1024], ld 3072)
    gemm_bf3<true><<<dim3(SQ / 128, SQ / 128, NB), blk>>>(
        qkv, qkv + INNERD, att, nullptr,
        INNERD, 3 * INNERD, 3 * INNERD, SQ, sQK, sQK, sAT, 0.125f);

    // 3) softmax rows
    softmax_rows<<<NB * SQ, blk>>>(att);

    // 4) ao = attn @ V, per batch        (NN: V stored [k=2048, n=1024] with ld 3072)
    gemm_bf3<false><<<dim3(INNERD / 128, SQ / 128, NB), blk>>>(
        att, qkv + 2 * INNERD, ao, nullptr,
        SQ, SQ, 3 * INNERD, INNERD, sAT, sQK, sAO, 1.f);

    // 5) out = ao @ W_out + b_out        (NN)
    gemm_bf3<false><<<dim3(DIMM / 128, MTOK / 128, 1), blk>>>(
        ao, Wout, out, bout,
        INNERD, INNERD, DIMM, DIMM, 0, 0, 0, 1.f);
}

// round 9
// speedup vs baseline: 2.1681x; 1.0898x over previous
#include <cuda_runtime.h>
#include <cuda_bf16.h>
#include <cstdint>
#include <math.h>

// Problem constants
#define NB     4
#define SQ     2048
#define DIMM   1024
#define INNERD 1024
#define MTOK   (NB * SQ)          // 8192

// Scratch (allocation-free rule: __device__ globals).
__device__ __align__(256) float g_qkv[(size_t)MTOK * 3 * INNERD];   // 96 MB
__device__ __align__(256) float g_att[(size_t)NB * SQ * SQ];        // 64 MB
__device__ __align__(256) float g_ao [(size_t)MTOK * INNERD];       // 32 MB

// ---------------- helpers ----------------
__device__ __forceinline__ uint32_t smem_u32(const void* p) {
    uint32_t a;
    asm("{ .reg .u64 t; cvta.to.shared.u64 t, %1; cvt.u32.u64 %0, t; }" : "=r"(a) : "l"(p));
    return a;
}

// Split 2 fp32 -> packed bf16 hi + bf16 lo (residual). Low 16 bits = first elem.
__device__ __forceinline__ void split2(float x0, float x1, unsigned& h, unsigned& l) {
    __nv_bfloat162 hh = __floats2bfloat162_rn(x0, x1);
    float r0 = x0 - __low2float(hh);
    float r1 = x1 - __high2float(hh);
    __nv_bfloat162 ll = __floats2bfloat162_rn(r0, r1);
    h = *reinterpret_cast<unsigned*>(&hh);
    l = *reinterpret_cast<unsigned*>(&ll);
}
// 8 consecutive fp32 (4 float2) -> uint4 hi + uint4 lo
__device__ __forceinline__ void split8(const float2* s, uint4& h, uint4& l) {
    split2(s[0].x, s[0].y, h.x, l.x);
    split2(s[1].x, s[1].y, h.y, l.y);
    split2(s[2].x, s[2].y, h.z, l.z);
    split2(s[3].x, s[3].y, h.w, l.w);
}

__device__ __forceinline__ void mma16(float* c, const unsigned* a, unsigned b0, unsigned b1) {
    asm volatile(
        "mma.sync.aligned.m16n8k16.row.col.f32.bf16.bf16.f32 "
        "{%0,%1,%2,%3}, {%4,%5,%6,%7}, {%8,%9}, {%0,%1,%2,%3};\n"
        : "+f"(c[0]), "+f"(c[1]), "+f"(c[2]), "+f"(c[3])
        : "r"(a[0]), "r"(a[1]), "r"(a[2]), "r"(a[3]), "r"(b0), "r"(b1));
}

__device__ __forceinline__ void ldsm4(uint32_t addr, unsigned* r) {
    asm volatile("ldmatrix.sync.aligned.m8n8.x4.shared.b16 {%0,%1,%2,%3}, [%4];"
        : "=r"(r[0]), "=r"(r[1]), "=r"(r[2]), "=r"(r[3]) : "r"(addr));
}

// Swizzled byte offset in a [128 rows][128 bytes] tile, 16B-group g in 0..7.
// Row layout: groups 0-3 = bf16 HI (k 0..31), groups 4-7 = bf16 LO (k 0..31).
__device__ __forceinline__ int swoff(int row, int g) {
    return row * 128 + (((unsigned)(g << 4)) ^ (((unsigned)row & 7) << 4));
}

// ---------------- 3xBF16 GEMM (static smem + ldmatrix) ----------------
// C = alpha * (A @ opB) (+ bias).
//   BT=true : B stored [N,K] row-major -> C = A @ B^T
//   BT=false: B stored [K,N] row-major -> C = A @ B
// CTA tile 128x128, K-chunk 32, 256 threads = 8 warps (4x2), warp tile 32x64.
// Static SMEM: two 16KB tiles (A and B), hi|lo packed per row.
// Global accesses are <=8B only (proven safe on harness pointers).
template <bool BT>
__global__ __launch_bounds__(256, 1)
void gemm_bf3(const float* __restrict__ A, const float* __restrict__ B,
              float* __restrict__ C, const float* __restrict__ bias,
              int K, int lda, int ldb, int ldc,
              long long sA, long long sB, long long sC, float alpha)
{
    __shared__ __align__(128) char tA[16384];
    __shared__ __align__(128) char tB[16384];
    const uint32_t sbA = smem_u32(tA);
    const uint32_t sbB = smem_u32(tB);

    const int tid = threadIdx.x;
    const int m0 = blockIdx.y * 128;
    const int n0 = blockIdx.x * 128;
    A += (long long)blockIdx.z * sA;
    B += (long long)blockIdx.z * sB;
    C += (long long)blockIdx.z * sC;

    const int warp = tid >> 5, lane = tid & 31;
    const int wm = warp >> 1;          // 0..3
    const int wn = warp & 1;           // 0..1

    // ---- fill mappings (chunk = 32 k) ----
    // A / B(NT): thread -> (row = tid>>2 + 64*i, span = tid&3), span = 8 floats
    const int ar  = tid >> 2;          // base row (+64 per i), 2 iters
    const int as  = tid & 3;           // 8-float span within the 32-k chunk
    // B(NN): thread -> (n = tid&127, span = (tid>>7) + 2*i)
    const int bn  = tid & 127;
    const int bs0 = tid >> 7;

    float2 stA[2][4], stB[2][4];
    float  stBn[2][8];

    auto load_chunk = [&](int k0) {
        #pragma unroll
        for (int i = 0; i < 2; i++) {
            int r = ar + i * 64;
            const float* p = A + (long long)(m0 + r) * lda + k0 + 8 * as;
            #pragma unroll
            for (int j = 0; j < 4; j++) stA[i][j] = *(const float2*)(p + 2 * j);
        }
        if (BT) {
            #pragma unroll
            for (int i = 0; i < 2; i++) {
                int r = ar + i * 64;
                const float* p = B + (long long)(n0 + r) * ldb + k0 + 8 * as;
                #pragma unroll
                for (int j = 0; j < 4; j++) stB[i][j] = *(const float2*)(p + 2 * j);
            }
        } else {
            #pragma unroll
            for (int i = 0; i < 2; i++) {
                int sp = bs0 + 2 * i;
                const float* p = B + (long long)(k0 + 8 * sp) * ldb + n0 + bn;
                #pragma unroll
                for (int j = 0; j < 8; j++) stBn[i][j] = p[(long long)j * ldb];
            }
        }
    };

    auto sts_chunk = [&]() {
        #pragma unroll
        for (int i = 0; i < 2; i++) {
            int r = ar + i * 64;
            uint4 h, l;
            split8(stA[i], h, l);
            *(uint4*)(tA + swoff(r, as))     = h;
            *(uint4*)(tA + swoff(r, as + 4)) = l;
        }
        if (BT) {
            #pragma unroll
            for (int i = 0; i < 2; i++) {
                int r = ar + i * 64;
                uint4 h, l;
                split8(stB[i], h, l);
                *(uint4*)(tB + swoff(r, as))     = h;
                *(uint4*)(tB + swoff(r, as + 4)) = l;
            }
        } else {
            #pragma unroll
            for (int i = 0; i < 2; i++) {
                int sp = bs0 + 2 * i;
                uint4 h, l;
                split2(stBn[i][0], stBn[i][1], h.x, l.x);
                split2(stBn[i][2], stBn[i][3], h.y, l.y);
                split2(stBn[i][4], stBn[i][5], h.z, l.z);
                split2(stBn[i][6], stBn[i][7], h.w, l.w);
                *(uint4*)(tB + swoff(bn, sp))     = h;
                *(uint4*)(tB + swoff(bn, sp + 4)) = l;
            }
        }
    };

    // ---- ldmatrix address components ----
    const int l15 = lane & 15;
    const int lh  = (lane >> 4) << 4;          // 0 or 16 bytes (k-half)
    const int s   = (l15 & 7) << 4;            // swizzle XOR
    const int rA0 = (wm * 32 + l15) * 128;     // A rows
    const int rA1 = rA0 + 16 * 128;
    const int rB0 = (wn * 64 + l15) * 128;     // B rows; +16*128 per p

    float acc[2][8][4] = {};

    const int nchunks = K >> 5;
    load_chunk(0);

    for (int c = 0; c < nchunks; c++) {
        __syncthreads();               // previous chunk fully consumed
        sts_chunk();
        __syncthreads();
        if (c + 1 < nchunks) load_chunk((c + 1) << 5);   // LDGs overlap compute

        #pragma unroll
        for (int ks = 0; ks < 2; ks++) {
            const int xh = ((ks << 5) + lh) ^ s;         // hi region bytes 0-63
            const int xl = (64 + (ks << 5) + lh) ^ s;    // lo region bytes 64-127
            unsigned ah[2][4], al[2][4];
            ldsm4(sbA + rA0 + xh, ah[0]);
            ldsm4(sbA + rA1 + xh, ah[1]);
            ldsm4(sbA + rA0 + xl, al[0]);
            ldsm4(sbA + rA1 + xl, al[1]);
            #pragma unroll
            for (int p = 0; p < 4; p++) {
                const int rb = rB0 + p * 16 * 128;
                unsigned bh[4], bl[4];
                ldsm4(sbB + rb + xh, bh);
                ldsm4(sbB + rb + xl, bl);
                #pragma unroll
                for (int mi = 0; mi < 2; mi++) {
                    mma16(acc[mi][2 * p    ], ah[mi], bh[0], bh[2]);
                    mma16(acc[mi][2 * p + 1], ah[mi], bh[1], bh[3]);
                    mma16(acc[mi][2 * p    ], ah[mi], bl[0], bl[2]);
                    mma16(acc[mi][2 * p + 1], ah[mi], bl[1], bl[3]);
                    mma16(acc[mi][2 * p    ], al[mi], bh[0], bh[2]);
                    mma16(acc[mi][2 * p + 1], al[mi], bh[1], bh[3]);
                }
            }
        }
    }

    // ---- epilogue: direct fragment stores (float2 = 8B, proven safe) ----
    const int gid = lane >> 2, tig = lane & 3;
    #pragma unroll
    for (int mi = 0; mi < 2; mi++) {
        #pragma unroll
        for (int ni = 0; ni < 8; ni++) {
            const int col  = n0 + wn * 64 + ni * 8 + 2 * tig;
            const int row0 = m0 + wm * 32 + mi * 16 + gid;
            float b0v = bias ? bias[col]     : 0.f;
            float b1v = bias ? bias[col + 1] : 0.f;
            float2 v0 = make_float2(acc[mi][ni][0] * alpha + b0v,
                                    acc[mi][ni][1] * alpha + b1v);
            float2 v1 = make_float2(acc[mi][ni][2] * alpha + b0v,
                                    acc[mi][ni][3] * alpha + b1v);
            *(float2*)(C + (long long)row0 * ldc + col)       = v0;
            *(float2*)(C + (long long)(row0 + 8) * ldc + col) = v1;
        }
    }
}

// ---------------- softmax ----------------
__global__ __launch_bounds__(256)
void softmax_rows(float* __restrict__ P)
{
    float* row = P + (long long)blockIdx.x * 2048;
    const int t = threadIdx.x;
    float v[8];
    float mx = -1e30f;
    #pragma unroll
    for (int j = 0; j < 8; j++) { v[j] = row[t + j * 256]; mx = fmaxf(mx, v[j]); }

    __shared__ float red[256];
    red[t] = mx; __syncthreads();
    for (int s = 128; s > 0; s >>= 1) {
        if (t < s) red[t] = fmaxf(red[t], red[t + s]);
        __syncthreads();
    }
    mx = red[0]; __syncthreads();

    float sum = 0.f;
    #pragma unroll
    for (int j = 0; j < 8; j++) { v[j] = __expf(v[j] - mx); sum += v[j]; }
    red[t] = sum; __syncthreads();
    for (int s = 128; s > 0; s >>= 1) {
        if (t < s) red[t] += red[t + s];
        __syncthreads();
    }
    const float inv = 1.f / red[0];
    #pragma unroll
    for (int j = 0; j < 8; j++) row[t + j * 256] = v[j] * inv;
}

// ---------------- launch ----------------
extern "C" void kernel_launch(void* const* d_in, const int* in_sizes, int n_in,
                              void* d_out, int out_size)
{
    const float* x    = (const float*)d_in[0];   // [4, 2048, 1024]
    const float* Wqkv = (const float*)d_in[1];   // [1024, 3072]
    const float* Wout = (const float*)d_in[2];   // [1024, 1024]
    const float* bout = (const float*)d_in[3];   // [1024]
    float* out = (float*)d_out;                  // [4, 2048, 1024]

    float *qkv, *att, *ao;
    cudaGetSymbolAddress((void**)&qkv, g_qkv);
    cudaGetSymbolAddress((void**)&att, g_att);
    cudaGetSymbolAddress((void**)&ao,  g_ao);

    const dim3 blk(256);
    const long long sQK = (long long)SQ * 3 * INNERD;
    const long long sAT = (long long)SQ * SQ;
    const long long sAO = (long long)SQ * INNERD;

    // 1) qkv = x @ W_qkv            [8192,1024]x[1024,3072] (NN)
    gemm_bf3<false><<<dim3(3 * INNERD / 128, MTOK / 128, 1), blk>>>(
        x, Wqkv, qkv, nullptr,
        DIMM, DIMM, 3 * INNERD, 3 * INNERD, 0, 0, 0, 1.f);

    // 2) logits = (Q @ K^T) * scale, per batch (NT)
    gemm_bf3<true><<<dim3(SQ / 128, SQ / 128, NB), blk>>>(
        qkv, qkv + INNERD, att, nullptr,
        INNERD, 3 * INNERD, 3 * INNERD, SQ, sQK, sQK, sAT, 0.125f);

    // 3) softmax rows
    softmax_rows<<<NB * SQ, blk>>>(att);

    // 4) ao = attn @ V, per batch (NN, V ld 3072)
    gemm_bf3<false><<<dim3(INNERD / 128, SQ / 128, NB), blk>>>(
        att, qkv + 2 * INNERD, ao, nullptr,
        SQ, SQ, 3 * INNERD, INNERD, sAT, sQK, sAO, 1.f);

    // 5) out = ao @ W_out + b_out (NN)
    gemm_bf3<false><<<dim3(DIMM / 128, MTOK / 128, 1), blk>>>(
        ao, Wout, out, bout,
        INNERD, INNERD, DIMM, DIMM, 0, 0, 0, 1.f);
}